// round 4
// baseline (speedup 1.0000x reference)
#include <cuda_runtime.h>
#include <cstddef>

// SparseConv2D: 3x3 conv (Cin=32 -> Cout=32) on 16x16 patches at stride 14,
// keep 14x14 interior, gate each block by max(mask block) > 0.5.
// f32x2 (FFMA2) packed-math version: output columns paired as {c, c+7}.

#define BSZ   16
#define STR   14
#define CIN   32
#define COUT  32
#define NBH   36
#define NBW   36
#define HIN   506
#define WIN   506
#define HOUT  504
#define WOUT  504

struct SmemLayout {
    float patch[BSZ][CIN][BSZ];      // 32 KB  [r][cin][c]  (c contiguous!)
    float wgt[3][3][CIN][COUT];      // 36 KB  [ky][kx][cin][cout]
    float red[8];
    float scale;
};

typedef unsigned long long u64;

__device__ __forceinline__ u64 pack2(float lo, float hi) {
    u64 r;
    asm("mov.b64 %0, {%1, %2};" : "=l"(r) : "f"(lo), "f"(hi));
    return r;
}
__device__ __forceinline__ void unpack2(u64 v, float& lo, float& hi) {
    asm("mov.b64 {%0, %1}, %2;" : "=f"(lo), "=f"(hi) : "l"(v));
}
__device__ __forceinline__ void ffma2(u64& acc, u64 a, u64 b) {
    asm("fma.rn.f32x2 %0, %1, %2, %0;" : "+l"(acc) : "l"(a), "l"(b));
}
__device__ __forceinline__ u64 add2(u64 a, u64 b) {
    u64 r; asm("add.rn.f32x2 %0, %1, %2;" : "=l"(r) : "l"(a), "l"(b)); return r;
}
__device__ __forceinline__ u64 mul2(u64 a, u64 b) {
    u64 r; asm("mul.rn.f32x2 %0, %1, %2;" : "=l"(r) : "l"(a), "l"(b)); return r;
}

__global__ __launch_bounds__(224, 3)
void sparse_conv3x3_kernel(const float* __restrict__ x,
                           const float* __restrict__ mask,
                           const float* __restrict__ wglob,
                           const float* __restrict__ bias,
                           float* __restrict__ out)
{
    extern __shared__ char smem_raw[];
    SmemLayout* sm = reinterpret_cast<SmemLayout*>(smem_raw);

    const int bw = blockIdx.x;          // block col 0..35
    const int bh = blockIdx.y;          // block row 0..35
    const int n  = blockIdx.z;          // batch 0..7
    const int tx = threadIdx.x;         // cout lane 0..31
    const int ty = threadIdx.y;         // row-pair 0..6
    const int tid = ty * 32 + tx;       // 0..223

    const int r0 = bh * STR;
    const int c0 = bw * STR;

    // ---- load weights (9216 floats = 2304 float4), layout unchanged ----
    {
        const float4* w4  = reinterpret_cast<const float4*>(wglob);
        float4*       sw4 = reinterpret_cast<float4*>(&sm->wgt[0][0][0][0]);
        #pragma unroll 1
        for (int i = tid; i < (3 * 3 * CIN * COUT) / 4; i += 224)
            sw4[i] = w4[i];
    }

    // ---- load 16x16x32 patch, transposing NHWC -> [r][cin][c] ----
    // e -> (r, cin4, c) with c fastest across lanes: STS is only 2-way conflicted.
    {
        #pragma unroll 1
        for (int e = tid; e < 2048; e += 224) {
            int c    = e & 15;
            int cin4 = (e >> 4) & 7;
            int r    = e >> 7;
            const float4 v = *(reinterpret_cast<const float4*>(
                x + (((size_t)n * HIN + (r0 + r)) * WIN + (c0 + c)) * CIN) + cin4);
            sm->patch[r][cin4 * 4 + 0][c] = v.x;
            sm->patch[r][cin4 * 4 + 1][c] = v.y;
            sm->patch[r][cin4 * 4 + 2][c] = v.z;
            sm->patch[r][cin4 * 4 + 3][c] = v.w;
        }
    }

    // ---- block-active mask: max over 16x16 mask patch ----
    {
        float m;
        {
            int r = tid >> 4, c = tid & 15;
            m = mask[((size_t)n * HIN + (r0 + r)) * WIN + (c0 + c)];
            if (tid < 32) {
                int j = tid + 224;
                int r2 = j >> 4, c2 = j & 15;
                m = fmaxf(m, mask[((size_t)n * HIN + (r0 + r2)) * WIN + (c0 + c2)]);
            }
        }
        #pragma unroll
        for (int off = 16; off; off >>= 1)
            m = fmaxf(m, __shfl_xor_sync(0xffffffffu, m, off));
        if (tx == 0) sm->red[ty] = m;
    }
    __syncthreads();
    if (tid == 0) {
        float mm = sm->red[0];
        #pragma unroll
        for (int i = 1; i < 7; i++) mm = fmaxf(mm, sm->red[i]);
        sm->scale = (mm > 0.5f) ? 1.0f : 0.0f;
    }
    __syncthreads();

    // ---- compute: 2 output rows per thread (rbase, rbase+1), cout = tx.
    //      acc pair j holds output columns {j, j+7}.  Tap row r needs x-pairs
    //      xp[t] = {row[t], row[t+7]}, t = 0..8 (pair for acc j, tap kx is xp[j+kx]).
    u64 acc0[7], acc1[7];
    #pragma unroll
    for (int j = 0; j < 7; j++) { acc0[j] = 0ull; acc1[j] = 0ull; }

    const int rbase = 2 * ty;

    #pragma unroll 1
    for (int cin = 0; cin < CIN; ++cin) {
        // weight pairs {w,w} for all 9 taps of this cin
        u64 w[3][3];
        #pragma unroll
        for (int ky = 0; ky < 3; ky++)
            #pragma unroll
            for (int kx = 0; kx < 3; kx++) {
                float ws = sm->wgt[ky][kx][cin][tx];
                w[ky][kx] = pack2(ws, ws);
            }

        #pragma unroll
        for (int r = 0; r < 4; ++r) {        // tap row rbase + r
            const float* row = &sm->patch[rbase + r][cin][0];
            float4 q0 = *reinterpret_cast<const float4*>(row + 0);
            float4 q1 = *reinterpret_cast<const float4*>(row + 4);
            float4 q2 = *reinterpret_cast<const float4*>(row + 8);
            float4 q3 = *reinterpret_cast<const float4*>(row + 12);
            float xv[16] = {q0.x, q0.y, q0.z, q0.w,
                            q1.x, q1.y, q1.z, q1.w,
                            q2.x, q2.y, q2.z, q2.w,
                            q3.x, q3.y, q3.z, q3.w};
            u64 xp[9];
            #pragma unroll
            for (int t = 0; t < 9; t++)
                xp[t] = pack2(xv[t], xv[t + 7]);

            // acc0 (output row rbase) uses ky = r for r in 0..2
            if (r < 3) {
                #pragma unroll
                for (int kx = 0; kx < 3; kx++)
                    #pragma unroll
                    for (int j = 0; j < 7; j++)
                        ffma2(acc0[j], xp[j + kx], w[r][kx]);
            }
            // acc1 (output row rbase+1) uses ky = r-1 for r in 1..3
            if (r >= 1) {
                #pragma unroll
                for (int kx = 0; kx < 3; kx++)
                    #pragma unroll
                    for (int j = 0; j < 7; j++)
                        ffma2(acc1[j], xp[j + kx], w[r - 1][kx]);
            }
        }
    }

    // ---- epilogue: (conv + bias) * active ----
    const float sc = sm->scale;
    const float b  = bias[tx];
    const u64 b2  = pack2(b, b);
    const u64 sc2 = pack2(sc, sc);

    const int orow = bh * STR + rbase;
    const int ocol = bw * STR;
    size_t obase = (((size_t)n * HOUT + orow) * WOUT + ocol) * COUT + tx;
    const size_t rstride = (size_t)WOUT * COUT;

    #pragma unroll
    for (int j = 0; j < 7; j++) {
        float lo, hi;
        u64 v0 = mul2(add2(acc0[j], b2), sc2);
        unpack2(v0, lo, hi);
        out[obase + (size_t)j * COUT]        = lo;
        out[obase + (size_t)(j + 7) * COUT]  = hi;
        u64 v1 = mul2(add2(acc1[j], b2), sc2);
        unpack2(v1, lo, hi);
        out[obase + rstride + (size_t)j * COUT]       = lo;
        out[obase + rstride + (size_t)(j + 7) * COUT] = hi;
    }
}

extern "C" void kernel_launch(void* const* d_in, const int* in_sizes, int n_in,
                              void* d_out, int out_size)
{
    const float* x    = (const float*)d_in[0];
    const float* mask = (const float*)d_in[1];
    const float* w    = (const float*)d_in[2];
    const float* bias = (const float*)d_in[3];
    float* out        = (float*)d_out;

    (void)in_sizes; (void)n_in; (void)out_size;

    cudaFuncSetAttribute(sparse_conv3x3_kernel,
                         cudaFuncAttributeMaxDynamicSharedMemorySize,
                         (int)sizeof(SmemLayout));

    dim3 grid(NBW, NBH, 8);
    dim3 block(32, 7);
    sparse_conv3x3_kernel<<<grid, block, sizeof(SmemLayout)>>>(x, mask, w, bias, out);
}

// round 5
// speedup vs baseline: 1.3368x; 1.3368x over previous
#include <cuda_runtime.h>
#include <cstddef>

// SparseConv2D: 3x3 conv (Cin=32 -> Cout=32) on 16x16 patches at stride 14,
// keep 14x14 interior, gate each block by max(mask block) > 0.5.
// Scalar-FFMA compute (FFMA peak = 1/cyc/SMSP on sm_103a) with c-contiguous
// patch layout so tap rows load as 4x LDS.128.

#define BSZ   16
#define STR   14
#define CIN   32
#define COUT  32
#define NBH   36
#define NBW   36
#define HIN   506
#define WIN   506
#define HOUT  504
#define WOUT  504

struct SmemLayout {
    float patch[BSZ][CIN][BSZ];      // 32 KB  [r][cin][c]  (c contiguous)
    float wgt[3][3][CIN][COUT];      // 36 KB  [ky][kx][cin][cout]
    float red[8];
    float scale;
};

__global__ __launch_bounds__(224, 3)
void sparse_conv3x3_kernel(const float* __restrict__ x,
                           const float* __restrict__ mask,
                           const float* __restrict__ wglob,
                           const float* __restrict__ bias,
                           float* __restrict__ out)
{
    extern __shared__ char smem_raw[];
    SmemLayout* sm = reinterpret_cast<SmemLayout*>(smem_raw);

    const int bw = blockIdx.x;          // block col 0..35
    const int bh = blockIdx.y;          // block row 0..35
    const int n  = blockIdx.z;          // batch 0..7
    const int tx = threadIdx.x;         // cout lane 0..31
    const int ty = threadIdx.y;         // row-pair 0..6
    const int tid = ty * 32 + tx;       // 0..223

    const int r0 = bh * STR;
    const int c0 = bw * STR;

    // ---- load weights (9216 floats = 2304 float4) ----
    {
        const float4* w4  = reinterpret_cast<const float4*>(wglob);
        float4*       sw4 = reinterpret_cast<float4*>(&sm->wgt[0][0][0][0]);
        #pragma unroll 1
        for (int i = tid; i < (3 * 3 * CIN * COUT) / 4; i += 224)
            sw4[i] = w4[i];
    }

    // ---- load 16x16x32 patch, transposing NHWC -> [r][cin][c] ----
    // e -> (r, cin4, c) with c fastest across lanes (STS ~2-way conflicted).
    {
        #pragma unroll 1
        for (int e = tid; e < 2048; e += 224) {
            int c    = e & 15;
            int cin4 = (e >> 4) & 7;
            int r    = e >> 7;
            const float4 v = *(reinterpret_cast<const float4*>(
                x + (((size_t)n * HIN + (r0 + r)) * WIN + (c0 + c)) * CIN) + cin4);
            sm->patch[r][cin4 * 4 + 0][c] = v.x;
            sm->patch[r][cin4 * 4 + 1][c] = v.y;
            sm->patch[r][cin4 * 4 + 2][c] = v.z;
            sm->patch[r][cin4 * 4 + 3][c] = v.w;
        }
    }

    // ---- block-active mask: max over 16x16 mask patch ----
    {
        float m;
        {
            int r = tid >> 4, c = tid & 15;
            m = mask[((size_t)n * HIN + (r0 + r)) * WIN + (c0 + c)];
            if (tid < 32) {
                int j = tid + 224;
                int r2 = j >> 4, c2 = j & 15;
                m = fmaxf(m, mask[((size_t)n * HIN + (r0 + r2)) * WIN + (c0 + c2)]);
            }
        }
        #pragma unroll
        for (int off = 16; off; off >>= 1)
            m = fmaxf(m, __shfl_xor_sync(0xffffffffu, m, off));
        if (tx == 0) sm->red[ty] = m;     // warp == fixed ty (blockDim.x == 32)
    }
    __syncthreads();
    if (tid == 0) {
        float mm = sm->red[0];
        #pragma unroll
        for (int i = 1; i < 7; i++) mm = fmaxf(mm, sm->red[i]);
        sm->scale = (mm > 0.5f) ? 1.0f : 0.0f;
    }
    __syncthreads();

    // ---- compute: each thread owns 2 adjacent output rows (2*ty, 2*ty+1),
    //      14 cols each, for cout = tx. Tap row (rbase+r) loads once per cin
    //      as 4x LDS.128 (warp-broadcast) and feeds both output rows. ----
    float acc0[14], acc1[14];
    #pragma unroll
    for (int i = 0; i < 14; i++) { acc0[i] = 0.0f; acc1[i] = 0.0f; }

    const int rbase = 2 * ty;           // output row pair base (0..12)

    #pragma unroll 1
    for (int cin = 0; cin < CIN; ++cin) {
        // 9 distinct weights this cin, shared by both output rows
        float w[3][3];
        #pragma unroll
        for (int ky = 0; ky < 3; ky++)
            #pragma unroll
            for (int kx = 0; kx < 3; kx++)
                w[ky][kx] = sm->wgt[ky][kx][cin][tx];

        #pragma unroll
        for (int r = 0; r < 4; ++r) {        // tap row rbase + r
            const float* row = &sm->patch[rbase + r][cin][0];
            float4 q0 = *reinterpret_cast<const float4*>(row + 0);
            float4 q1 = *reinterpret_cast<const float4*>(row + 4);
            float4 q2 = *reinterpret_cast<const float4*>(row + 8);
            float4 q3 = *reinterpret_cast<const float4*>(row + 12);
            float xv[16] = {q0.x, q0.y, q0.z, q0.w,
                            q1.x, q1.y, q1.z, q1.w,
                            q2.x, q2.y, q2.z, q2.w,
                            q3.x, q3.y, q3.z, q3.w};

            // output row rbase uses tap rows rbase+0..2 (ky = r)
            if (r < 3) {
                #pragma unroll
                for (int kx = 0; kx < 3; kx++) {
                    float wv = w[r][kx];
                    #pragma unroll
                    for (int c = 0; c < 14; c++)
                        acc0[c] = fmaf(xv[c + kx], wv, acc0[c]);
                }
            }
            // output row rbase+1 uses tap rows rbase+1..3 (ky = r-1)
            if (r >= 1) {
                #pragma unroll
                for (int kx = 0; kx < 3; kx++) {
                    float wv = w[r - 1][kx];
                    #pragma unroll
                    for (int c = 0; c < 14; c++)
                        acc1[c] = fmaf(xv[c + kx], wv, acc1[c]);
                }
            }
        }
    }

    // ---- epilogue: (conv + bias) * active ----
    const float sc = sm->scale;
    const float b  = bias[tx];
    const int orow = bh * STR + rbase;
    const int ocol = bw * STR;
    size_t obase = (((size_t)n * HOUT + orow) * WOUT + ocol) * COUT + tx;
    const size_t rstride = (size_t)WOUT * COUT;
    #pragma unroll
    for (int c = 0; c < 14; c++) {
        out[obase + (size_t)c * COUT]           = (acc0[c] + b) * sc;
        out[obase + rstride + (size_t)c * COUT] = (acc1[c] + b) * sc;
    }
}

extern "C" void kernel_launch(void* const* d_in, const int* in_sizes, int n_in,
                              void* d_out, int out_size)
{
    const float* x    = (const float*)d_in[0];
    const float* mask = (const float*)d_in[1];
    const float* w    = (const float*)d_in[2];
    const float* bias = (const float*)d_in[3];
    float* out        = (float*)d_out;

    (void)in_sizes; (void)n_in; (void)out_size;

    cudaFuncSetAttribute(sparse_conv3x3_kernel,
                         cudaFuncAttributeMaxDynamicSharedMemorySize,
                         (int)sizeof(SmemLayout));

    dim3 grid(NBW, NBH, 8);
    dim3 block(32, 7);
    sparse_conv3x3_kernel<<<grid, block, sizeof(SmemLayout)>>>(x, mask, w, bias, out);
}

// round 6
// speedup vs baseline: 1.3378x; 1.0007x over previous
#include <cuda_runtime.h>
#include <cstddef>

// SparseConv2D: 3x3 conv (Cin=32 -> Cout=32) on 16x16 patches at stride 14,
// keep 14x14 interior, gate each block by max(mask block) > 0.5.
// Scalar-FFMA compute (FFMA peak = 1/cyc/SMSP on sm_103a) with c-contiguous
// patch layout so tap rows load as 4x LDS.128.

#define BSZ   16
#define STR   14
#define CIN   32
#define COUT  32
#define NBH   36
#define NBW   36
#define HIN   506
#define WIN   506
#define HOUT  504
#define WOUT  504

struct SmemLayout {
    float patch[BSZ][CIN][BSZ];      // 32 KB  [r][cin][c]  (c contiguous)
    float wgt[3][3][CIN][COUT];      // 36 KB  [ky][kx][cin][cout]
    float red[8];
    float scale;
};

__global__ __launch_bounds__(224, 3)
void sparse_conv3x3_kernel(const float* __restrict__ x,
                           const float* __restrict__ mask,
                           const float* __restrict__ wglob,
                           const float* __restrict__ bias,
                           float* __restrict__ out)
{
    extern __shared__ char smem_raw[];
    SmemLayout* sm = reinterpret_cast<SmemLayout*>(smem_raw);

    const int bw = blockIdx.x;          // block col 0..35
    const int bh = blockIdx.y;          // block row 0..35
    const int n  = blockIdx.z;          // batch 0..7
    const int tx = threadIdx.x;         // cout lane 0..31
    const int ty = threadIdx.y;         // row-pair 0..6
    const int tid = ty * 32 + tx;       // 0..223

    const int r0 = bh * STR;
    const int c0 = bw * STR;

    // ---- load weights (9216 floats = 2304 float4) ----
    {
        const float4* w4  = reinterpret_cast<const float4*>(wglob);
        float4*       sw4 = reinterpret_cast<float4*>(&sm->wgt[0][0][0][0]);
        #pragma unroll 1
        for (int i = tid; i < (3 * 3 * CIN * COUT) / 4; i += 224)
            sw4[i] = w4[i];
    }

    // ---- load 16x16x32 patch, transposing NHWC -> [r][cin][c] ----
    // e -> (r, cin4, c) with c fastest across lanes (STS ~2-way conflicted).
    {
        #pragma unroll 1
        for (int e = tid; e < 2048; e += 224) {
            int c    = e & 15;
            int cin4 = (e >> 4) & 7;
            int r    = e >> 7;
            const float4 v = *(reinterpret_cast<const float4*>(
                x + (((size_t)n * HIN + (r0 + r)) * WIN + (c0 + c)) * CIN) + cin4);
            sm->patch[r][cin4 * 4 + 0][c] = v.x;
            sm->patch[r][cin4 * 4 + 1][c] = v.y;
            sm->patch[r][cin4 * 4 + 2][c] = v.z;
            sm->patch[r][cin4 * 4 + 3][c] = v.w;
        }
    }

    // ---- block-active mask: max over 16x16 mask patch ----
    {
        float m;
        {
            int r = tid >> 4, c = tid & 15;
            m = mask[((size_t)n * HIN + (r0 + r)) * WIN + (c0 + c)];
            if (tid < 32) {
                int j = tid + 224;
                int r2 = j >> 4, c2 = j & 15;
                m = fmaxf(m, mask[((size_t)n * HIN + (r0 + r2)) * WIN + (c0 + c2)]);
            }
        }
        #pragma unroll
        for (int off = 16; off; off >>= 1)
            m = fmaxf(m, __shfl_xor_sync(0xffffffffu, m, off));
        if (tx == 0) sm->red[ty] = m;     // warp == fixed ty (blockDim.x == 32)
    }
    __syncthreads();
    if (tid == 0) {
        float mm = sm->red[0];
        #pragma unroll
        for (int i = 1; i < 7; i++) mm = fmaxf(mm, sm->red[i]);
        sm->scale = (mm > 0.5f) ? 1.0f : 0.0f;
    }
    __syncthreads();

    // ---- compute: each thread owns 2 adjacent output rows (2*ty, 2*ty+1),
    //      14 cols each, for cout = tx. Tap row (rbase+r) loads once per cin
    //      as 4x LDS.128 (warp-broadcast) and feeds both output rows. ----
    float acc0[14], acc1[14];
    #pragma unroll
    for (int i = 0; i < 14; i++) { acc0[i] = 0.0f; acc1[i] = 0.0f; }

    const int rbase = 2 * ty;           // output row pair base (0..12)

    #pragma unroll 1
    for (int cin = 0; cin < CIN; ++cin) {
        // 9 distinct weights this cin, shared by both output rows
        float w[3][3];
        #pragma unroll
        for (int ky = 0; ky < 3; ky++)
            #pragma unroll
            for (int kx = 0; kx < 3; kx++)
                w[ky][kx] = sm->wgt[ky][kx][cin][tx];

        #pragma unroll
        for (int r = 0; r < 4; ++r) {        // tap row rbase + r
            const float* row = &sm->patch[rbase + r][cin][0];
            float4 q0 = *reinterpret_cast<const float4*>(row + 0);
            float4 q1 = *reinterpret_cast<const float4*>(row + 4);
            float4 q2 = *reinterpret_cast<const float4*>(row + 8);
            float4 q3 = *reinterpret_cast<const float4*>(row + 12);
            float xv[16] = {q0.x, q0.y, q0.z, q0.w,
                            q1.x, q1.y, q1.z, q1.w,
                            q2.x, q2.y, q2.z, q2.w,
                            q3.x, q3.y, q3.z, q3.w};

            // output row rbase uses tap rows rbase+0..2 (ky = r)
            if (r < 3) {
                #pragma unroll
                for (int kx = 0; kx < 3; kx++) {
                    float wv = w[r][kx];
                    #pragma unroll
                    for (int c = 0; c < 14; c++)
                        acc0[c] = fmaf(xv[c + kx], wv, acc0[c]);
                }
            }
            // output row rbase+1 uses tap rows rbase+1..3 (ky = r-1)
            if (r >= 1) {
                #pragma unroll
                for (int kx = 0; kx < 3; kx++) {
                    float wv = w[r - 1][kx];
                    #pragma unroll
                    for (int c = 0; c < 14; c++)
                        acc1[c] = fmaf(xv[c + kx], wv, acc1[c]);
                }
            }
        }
    }

    // ---- epilogue: (conv + bias) * active ----
    const float sc = sm->scale;
    const float b  = bias[tx];
    const int orow = bh * STR + rbase;
    const int ocol = bw * STR;
    size_t obase = (((size_t)n * HOUT + orow) * WOUT + ocol) * COUT + tx;
    const size_t rstride = (size_t)WOUT * COUT;
    #pragma unroll
    for (int c = 0; c < 14; c++) {
        out[obase + (size_t)c * COUT]           = (acc0[c] + b) * sc;
        out[obase + rstride + (size_t)c * COUT] = (acc1[c] + b) * sc;
    }
}

extern "C" void kernel_launch(void* const* d_in, const int* in_sizes, int n_in,
                              void* d_out, int out_size)
{
    const float* x    = (const float*)d_in[0];
    const float* mask = (const float*)d_in[1];
    const float* w    = (const float*)d_in[2];
    const float* bias = (const float*)d_in[3];
    float* out        = (float*)d_out;

    (void)in_sizes; (void)n_in; (void)out_size;

    cudaFuncSetAttribute(sparse_conv3x3_kernel,
                         cudaFuncAttributeMaxDynamicSharedMemorySize,
                         (int)sizeof(SmemLayout));

    dim3 grid(NBW, NBH, 8);
    dim3 block(32, 7);
    sparse_conv3x3_kernel<<<grid, block, sizeof(SmemLayout)>>>(x, mask, w, bias, out);
}

// round 9
// speedup vs baseline: 1.5188x; 1.1353x over previous
#include <cuda_runtime.h>
#include <cstdint>
#include <cstddef>

// SparseConv2D via legacy mma.sync (tf32, m16n8k8) implicit GEMM.
// out(h,c,co) = sum_{ky,kx,ci} x(h+ky, c+kx, ci) * w[ky][kx][ci][co],
// gated per 14x14 block by max(mask) > 0.5 (precomputed into g_scale).
//
// Tile: one output row h, 128 output columns, all 32 cout. Persistent CTAs.
// Warp = 16 px x 32 cout, K = 9 taps x 32 cin, tf32 fragments from smem.

#define HIN   506
#define WIN   506
#define HOUT  504
#define WOUT  504
#define NB    36
#define TPR   4
#define NTILES (8 * HOUT * TPR)   // 16128
#define GRID_MAIN 304

// smem word layout (tf32 bits stored as u32):
//  patch: 3 ky buffers of [130 px][stride 36] -> 4680 words each, 14040 total
//  BS:    swizzled B frags [9 tap][4 cc][4 s][32 lane] uint2 -> 9216 words
//  bias:  32 words
#define PATCH_STRIDE 36
#define KY_WORDS     (130 * PATCH_STRIDE)      // 4680
#define PATCH_WORDS  (3 * KY_WORDS)            // 14040
#define BS_WOFF      PATCH_WORDS               // 14040
#define BIAS_WOFF    (BS_WOFF + 9216)          // 23256
#define SMEM_WORDS   (BIAS_WOFF + 32)          // 23288
#define SMEM_BYTES   (SMEM_WORDS * 4)          // 93152

__device__ float g_scale[8 * NB * NB];

__device__ __forceinline__ uint32_t f2tf(float f) {
    uint32_t r;
    asm("cvt.rna.tf32.f32 %0, %1;" : "=r"(r) : "f"(f));
    return r;
}

__device__ __forceinline__ void mma_tf32(float* c, uint32_t a0, uint32_t a1,
                                         uint32_t a2, uint32_t a3,
                                         uint32_t b0, uint32_t b1) {
    asm volatile("mma.sync.aligned.m16n8k8.row.col.f32.tf32.tf32.f32 "
                 "{%0,%1,%2,%3}, {%4,%5,%6,%7}, {%8,%9}, {%0,%1,%2,%3};"
                 : "+f"(c[0]), "+f"(c[1]), "+f"(c[2]), "+f"(c[3])
                 : "r"(a0), "r"(a1), "r"(a2), "r"(a3), "r"(b0), "r"(b1));
}

// ---------------- mask precompute: one CTA per (n,bh,bw) ----------------
__global__ void mask_kernel(const float* __restrict__ mask) {
    __shared__ float red[8];
    int b = blockIdx.x;
    int n = b / (NB * NB);
    int rem = b % (NB * NB);
    int bh = rem / NB, bw = rem % NB;
    int tid = threadIdx.x;              // 256 = 16x16
    int r = tid >> 4, c = tid & 15;
    float m = mask[((size_t)(n * HIN + bh * 14 + r)) * WIN + bw * 14 + c];
    #pragma unroll
    for (int off = 16; off; off >>= 1)
        m = fmaxf(m, __shfl_xor_sync(0xffffffffu, m, off));
    if ((tid & 31) == 0) red[tid >> 5] = m;
    __syncthreads();
    if (tid == 0) {
        float mm = red[0];
        #pragma unroll
        for (int i = 1; i < 8; i++) mm = fmaxf(mm, red[i]);
        g_scale[b] = (mm > 0.5f) ? 1.0f : 0.0f;
    }
}

// ---------------- main persistent kernel ----------------
__global__ __launch_bounds__(256, 2)
void conv_mma_kernel(const float* __restrict__ x,
                     const float* __restrict__ wglob,
                     const float* __restrict__ bias,
                     float* __restrict__ out)
{
    extern __shared__ uint32_t sp[];
    const int tid  = threadIdx.x;
    const int wid  = tid >> 5;
    const int lane = tid & 31;
    const int g    = lane >> 2;     // fragment group row 0..7
    const int tq   = lane & 3;      // thread-in-group 0..3

    // ---- build B once per CTA ----
    // stage raw weights into patch area (36864B <= 56160B)
    {
        const float4* w4 = reinterpret_cast<const float4*>(wglob);
        float4* st4 = reinterpret_cast<float4*>(sp);
        #pragma unroll 1
        for (int i = tid; i < 9216 / 4; i += 256)
            st4[i] = w4[i];
    }
    if (tid < 32) sp[BIAS_WOFF + tid] = __float_as_uint(bias[tid]);
    __syncthreads();
    // swizzle into fragment order: BS[tap][cc][s][lane] = {b0, b1}
    //   b0 = w[tap][cc*8 + (lane&3)    ][s*8 + lane>>2]
    //   b1 = w[tap][cc*8 + (lane&3) + 4][s*8 + lane>>2]
    {
        const float* stage = reinterpret_cast<const float*>(sp);
        #pragma unroll 1
        for (int idx = tid; idx < 4608; idx += 256) {
            int l   = idx & 31;
            int s   = (idx >> 5) & 3;
            int cc  = (idx >> 7) & 3;
            int tap = idx >> 9;
            int k   = cc * 8 + (l & 3);
            int n   = s * 8 + (l >> 2);
            uint32_t b0 = f2tf(stage[tap * 1024 + k * 32 + n]);
            uint32_t b1 = f2tf(stage[tap * 1024 + (k + 4) * 32 + n]);
            // write AFTER all reads of stage? guard with per-iteration hazard:
            // stage region [0,9216) and BS region [14040,...) are disjoint -> safe
            sp[BS_WOFF + idx * 2]     = b0;
            sp[BS_WOFF + idx * 2 + 1] = b1;
        }
    }
    __syncthreads();

    // ---- persistent tile loop ----
    for (int t = blockIdx.x; t < NTILES; t += GRID_MAIN) {
        const int n   = t / (HOUT * TPR);
        const int rem = t % (HOUT * TPR);
        const int h   = rem >> 2;
        const int c0  = (rem & 3) << 7;

        // build A: 3 ky rows x 130 px x 32 cin (tf32), row stride 36 words
        #pragma unroll 1
        for (int id = tid; id < 3120; id += 256) {
            int c4 = id & 7;
            int jj = id >> 3;
            int j  = jj % 130;
            int ky = jj / 130;
            int col = c0 + j; if (col > 505) col = 505;
            const float4 v = *reinterpret_cast<const float4*>(
                x + (((size_t)(n * HIN + h + ky)) * WIN + col) * 32 + c4 * 4);
            uint32_t* dst = sp + ky * KY_WORDS + j * PATCH_STRIDE + c4 * 4;
            dst[0] = f2tf(v.x);
            dst[1] = f2tf(v.y);
            dst[2] = f2tf(v.z);
            dst[3] = f2tf(v.w);
        }
        __syncthreads();

        // compute: warp wid handles px [wid*16, wid*16+16), cout 0..31
        float acc[4][4];   // [s][c0..c3]
        #pragma unroll
        for (int s = 0; s < 4; s++)
            #pragma unroll
            for (int i = 0; i < 4; i++) acc[s][i] = 0.0f;

        const int pbase = wid * 16;

        #pragma unroll 1
        for (int ky = 0; ky < 3; ky++) {
            const uint32_t* kbuf = sp + ky * KY_WORDS;
            #pragma unroll
            for (int kx = 0; kx < 3; kx++) {
                const int tap = ky * 3 + kx;
                const uint32_t* arow = kbuf + (pbase + kx + g) * PATCH_STRIDE + tq;
                const uint32_t* brow = sp + BS_WOFF + tap * 1024 + lane * 2;
                #pragma unroll
                for (int cc = 0; cc < 4; cc++) {
                    uint32_t a0 = arow[cc * 8];
                    uint32_t a1 = arow[cc * 8 + 8 * PATCH_STRIDE];
                    uint32_t a2 = arow[cc * 8 + 4];
                    uint32_t a3 = arow[cc * 8 + 8 * PATCH_STRIDE + 4];
                    #pragma unroll
                    for (int s = 0; s < 4; s++) {
                        const uint2 bb = *reinterpret_cast<const uint2*>(
                            brow + cc * 256 + s * 64);
                        mma_tf32(acc[s], a0, a1, a2, a3, bb.x, bb.y);
                    }
                }
            }
        }

        // epilogue: thread owns px {pbase+g, pbase+g+8}, couts s*8+2*tq+{0,1}
        {
            const float* bias_s = reinterpret_cast<const float*>(sp + BIAS_WOFF);
            const int colA = c0 + pbase + g;
            const int colB = colA + 8;
            const int srow = (n * NB + h / 14) * NB;
            float scA = 0.0f, scB = 0.0f;
            if (colA < WOUT) scA = g_scale[srow + colA / 14];
            if (colB < WOUT) scB = g_scale[srow + colB / 14];
            float* opA = out + ((size_t)(n * HOUT + h) * WOUT + colA) * 32;
            float* opB = out + ((size_t)(n * HOUT + h) * WOUT + colB) * 32;
            #pragma unroll
            for (int s = 0; s < 4; s++) {
                const int co = s * 8 + 2 * tq;
                const float b0 = bias_s[co], b1 = bias_s[co + 1];
                if (colA < WOUT) {
                    float2 v = make_float2((acc[s][0] + b0) * scA,
                                           (acc[s][1] + b1) * scA);
                    *reinterpret_cast<float2*>(opA + co) = v;
                }
                if (colB < WOUT) {
                    float2 v = make_float2((acc[s][2] + b0) * scB,
                                           (acc[s][3] + b1) * scB);
                    *reinterpret_cast<float2*>(opB + co) = v;
                }
            }
        }
        __syncthreads();   // all reads of patch done before next build
    }
}

extern "C" void kernel_launch(void* const* d_in, const int* in_sizes, int n_in,
                              void* d_out, int out_size)
{
    const float* x    = (const float*)d_in[0];
    const float* mask = (const float*)d_in[1];
    const float* w    = (const float*)d_in[2];
    const float* bias = (const float*)d_in[3];
    float* out        = (float*)d_out;
    (void)in_sizes; (void)n_in; (void)out_size;

    cudaFuncSetAttribute(conv_mma_kernel,
                         cudaFuncAttributeMaxDynamicSharedMemorySize, SMEM_BYTES);

    mask_kernel<<<8 * NB * NB, 256>>>(mask);
    conv_mma_kernel<<<GRID_MAIN, 256, SMEM_BYTES>>>(x, w, bias, out);
}

// round 11
// speedup vs baseline: 3.3133x; 2.1815x over previous
#include <cuda_runtime.h>
#include <cstdint>
#include <cstddef>

// SparseConv2D via mma.sync (tf32, m16n8k8) implicit GEMM, rolling-row strips.
// out(h,c,co) = sum_{ky,kx,ci} x(h+ky, c+kx, ci) * w[ky][kx][ci][co],
// gated per 14x14 block by max(mask) > 0.5 (precomputed into g_scale).
//
// Persistent CTA owns a (56 output rows x 128 cols) strip, sweeps h with a
// 3-slot ring of input-row buffers (slot = row % 3): one new row per iter,
// prefetched into registers during compute, stored after the barrier.

#define HIN   506
#define WIN   506
#define HOUT  504
#define WOUT  504
#define NB    36

#define NSTRIPS        32        // 8 batch * 4 column strips
#define CTAS_PER_STRIP 9
#define ROWS_PER_CTA   56        // 504 / 9
#define GRID_MAIN      (NSTRIPS * CTAS_PER_STRIP)   // 288

// smem word layout (tf32 bits stored as u32):
//  ring:  3 slots of [130 px][stride 36] -> 4680 words each, 14040 total
//  BS:    swizzled B frags [9 tap][4 cc][4 s][32 lane] uint2 -> 9216 words
//  bias:  32 words
#define PATCH_STRIDE 36
#define KY_WORDS     (130 * PATCH_STRIDE)      // 4680
#define PATCH_WORDS  (3 * KY_WORDS)            // 14040
#define BS_WOFF      PATCH_WORDS               // 14040
#define BIAS_WOFF    (BS_WOFF + 9216)          // 23256
#define SMEM_WORDS   (BIAS_WOFF + 32)          // 23288
#define SMEM_BYTES   (SMEM_WORDS * 4)          // 93152

__device__ float g_scale[8 * NB * NB];

__device__ __forceinline__ uint32_t f2tf(float f) {
    uint32_t r;
    asm("cvt.rna.tf32.f32 %0, %1;" : "=r"(r) : "f"(f));
    return r;
}

__device__ __forceinline__ void mma_tf32(float* c, uint32_t a0, uint32_t a1,
                                         uint32_t a2, uint32_t a3,
                                         uint32_t b0, uint32_t b1) {
    asm volatile("mma.sync.aligned.m16n8k8.row.col.f32.tf32.tf32.f32 "
                 "{%0,%1,%2,%3}, {%4,%5,%6,%7}, {%8,%9}, {%0,%1,%2,%3};"
                 : "+f"(c[0]), "+f"(c[1]), "+f"(c[2]), "+f"(c[3])
                 : "r"(a0), "r"(a1), "r"(a2), "r"(a3), "r"(b0), "r"(b1));
}

// ---------------- mask precompute: one CTA per (n,bh,bw) ----------------
__global__ void mask_kernel(const float* __restrict__ mask) {
    __shared__ float red[8];
    int b = blockIdx.x;
    int n = b / (NB * NB);
    int rem = b % (NB * NB);
    int bh = rem / NB, bw = rem % NB;
    int tid = threadIdx.x;              // 256 = 16x16
    int r = tid >> 4, c = tid & 15;
    float m = mask[((size_t)(n * HIN + bh * 14 + r)) * WIN + bw * 14 + c];
    #pragma unroll
    for (int off = 16; off; off >>= 1)
        m = fmaxf(m, __shfl_xor_sync(0xffffffffu, m, off));
    if ((tid & 31) == 0) red[tid >> 5] = m;
    __syncthreads();
    if (tid == 0) {
        float mm = red[0];
        #pragma unroll
        for (int i = 1; i < 8; i++) mm = fmaxf(mm, red[i]);
        g_scale[b] = (mm > 0.5f) ? 1.0f : 0.0f;
    }
}

// ---------------- main persistent kernel ----------------
__global__ __launch_bounds__(256, 2)
void conv_mma_kernel(const float* __restrict__ x,
                     const float* __restrict__ wglob,
                     const float* __restrict__ bias,
                     float* __restrict__ out)
{
    extern __shared__ uint32_t sp[];
    const int tid  = threadIdx.x;
    const int wid  = tid >> 5;
    const int lane = tid & 31;
    const int g    = lane >> 2;     // fragment group row 0..7
    const int tq   = lane & 3;      // thread-in-group 0..3

    // ---- strip / row-range assignment ----
    const int strip  = blockIdx.x / CTAS_PER_STRIP;       // 0..31
    const int rchunk = blockIdx.x % CTAS_PER_STRIP;       // 0..8
    const int n      = strip >> 2;                        // batch
    const int c0     = (strip & 3) << 7;                  // col base
    const int hstart = rchunk * ROWS_PER_CTA;
    const int hend   = hstart + ROWS_PER_CTA;

    // ---- build B once per CTA (stage raw weights in ring area, then swizzle) ----
    {
        const float4* w4 = reinterpret_cast<const float4*>(wglob);
        float4* st4 = reinterpret_cast<float4*>(sp);
        #pragma unroll 1
        for (int i = tid; i < 9216 / 4; i += 256)
            st4[i] = w4[i];
    }
    if (tid < 32) sp[BIAS_WOFF + tid] = __float_as_uint(bias[tid]);
    __syncthreads();
    {
        const float* stage = reinterpret_cast<const float*>(sp);
        #pragma unroll 1
        for (int idx = tid; idx < 4608; idx += 256) {
            int l   = idx & 31;
            int s   = (idx >> 5) & 3;
            int cc  = (idx >> 7) & 3;
            int tap = idx >> 9;
            int k   = cc * 8 + (l & 3);
            int nn  = s * 8 + (l >> 2);
            uint32_t b0 = f2tf(stage[tap * 1024 + k * 32 + nn]);
            uint32_t b1 = f2tf(stage[tap * 1024 + (k + 4) * 32 + nn]);
            sp[BS_WOFF + idx * 2]     = b0;
            sp[BS_WOFF + idx * 2 + 1] = b1;
        }
    }
    __syncthreads();

    // ---- initial build: input rows hstart .. hstart+2 into ring slots ----
    #pragma unroll 1
    for (int id = tid; id < 3120; id += 256) {
        int c4 = id & 7;
        int jj = id >> 3;
        int j  = jj % 130;
        int ky = jj / 130;
        int row = hstart + ky;
        int col = c0 + j; if (col > 505) col = 505;
        const float4 v = *reinterpret_cast<const float4*>(
            x + (((size_t)(n * HIN + row)) * WIN + col) * 32 + c4 * 4);
        uint32_t* dst = sp + (row % 3) * KY_WORDS + j * PATCH_STRIDE + c4 * 4;
        dst[0] = f2tf(v.x);
        dst[1] = f2tf(v.y);
        dst[2] = f2tf(v.z);
        dst[3] = f2tf(v.w);
    }
    __syncthreads();

    const int pbase = wid * 16;

    // ---- rolling sweep over output rows ----
    #pragma unroll 1
    for (int h = hstart; h < hend; ++h) {
        // prefetch next input row (h+3) into registers during compute
        const bool havepf = (h + 1 < hend);
        float4 pf[5];
        if (havepf) {
            const int prow = h + 3;              // <= hend+1 <= 505
            #pragma unroll
            for (int k = 0; k < 5; k++) {
                int id = tid + k * 256;
                if (id < 1040) {
                    int c4 = id & 7;
                    int j  = id >> 3;
                    int col = c0 + j; if (col > 505) col = 505;
                    pf[k] = *reinterpret_cast<const float4*>(
                        x + (((size_t)(n * HIN + prow)) * WIN + col) * 32 + c4 * 4);
                }
            }
        }

        // compute: warp handles px [pbase, pbase+16), cout 0..31
        float acc[4][4];
        #pragma unroll
        for (int s = 0; s < 4; s++)
            #pragma unroll
            for (int i = 0; i < 4; i++) acc[s][i] = 0.0f;

        #pragma unroll 1
        for (int ky = 0; ky < 3; ky++) {
            const uint32_t* kbuf = sp + ((h + ky) % 3) * KY_WORDS;
            #pragma unroll
            for (int kx = 0; kx < 3; kx++) {
                const int tap = ky * 3 + kx;
                const uint32_t* arow = kbuf + (pbase + kx + g) * PATCH_STRIDE + tq;
                const uint32_t* brow = sp + BS_WOFF + tap * 1024 + lane * 2;
                #pragma unroll
                for (int cc = 0; cc < 4; cc++) {
                    uint32_t a0 = arow[cc * 8];
                    uint32_t a1 = arow[cc * 8 + 8 * PATCH_STRIDE];
                    uint32_t a2 = arow[cc * 8 + 4];
                    uint32_t a3 = arow[cc * 8 + 8 * PATCH_STRIDE + 4];
                    #pragma unroll
                    for (int s = 0; s < 4; s++) {
                        const uint2 bb = *reinterpret_cast<const uint2*>(
                            brow + cc * 256 + s * 64);
                        mma_tf32(acc[s], a0, a1, a2, a3, bb.x, bb.y);
                    }
                }
            }
        }

        // epilogue: thread owns px {pbase+g, pbase+g+8}, couts s*8+2*tq+{0,1}
        {
            const float* bias_s = reinterpret_cast<const float*>(sp + BIAS_WOFF);
            const int colA = c0 + pbase + g;
            const int colB = colA + 8;
            const int srow = (n * NB + h / 14) * NB;
            float scA = 0.0f, scB = 0.0f;
            if (colA < WOUT) scA = g_scale[srow + colA / 14];
            if (colB < WOUT) scB = g_scale[srow + colB / 14];
            float* opA = out + ((size_t)(n * HOUT + h) * WOUT + colA) * 32;
            float* opB = out + ((size_t)(n * HOUT + h) * WOUT + colB) * 32;
            #pragma unroll
            for (int s = 0; s < 4; s++) {
                const int co = s * 8 + 2 * tq;
                const float b0 = bias_s[co], b1 = bias_s[co + 1];
                if (colA < WOUT) {
                    float2 v = make_float2((acc[s][0] + b0) * scA,
                                           (acc[s][1] + b1) * scA);
                    *reinterpret_cast<float2*>(opA + co) = v;
                }
                if (colB < WOUT) {
                    float2 v = make_float2((acc[s][2] + b0) * scB,
                                           (acc[s][3] + b1) * scB);
                    *reinterpret_cast<float2*>(opB + co) = v;
                }
            }
        }

        __syncthreads();     // everyone done reading ring slot h%3

        if (havepf) {
            const int slot = h % 3;          // == (h+3) % 3
            #pragma unroll
            for (int k = 0; k < 5; k++) {
                int id = tid + k * 256;
                if (id < 1040) {
                    int c4 = id & 7;
                    int j  = id >> 3;
                    uint32_t* dst = sp + slot * KY_WORDS + j * PATCH_STRIDE + c4 * 4;
                    dst[0] = f2tf(pf[k].x);
                    dst[1] = f2tf(pf[k].y);
                    dst[2] = f2tf(pf[k].z);
                    dst[3] = f2tf(pf[k].w);
                }
            }
        }
        __syncthreads();     // new row visible before next compute
    }
}

extern "C" void kernel_launch(void* const* d_in, const int* in_sizes, int n_in,
                              void* d_out, int out_size)
{
    const float* x    = (const float*)d_in[0];
    const float* mask = (const float*)d_in[1];
    const float* w    = (const float*)d_in[2];
    const float* bias = (const float*)d_in[3];
    float* out        = (float*)d_out;
    (void)in_sizes; (void)n_in; (void)out_size;

    cudaFuncSetAttribute(conv_mma_kernel,
                         cudaFuncAttributeMaxDynamicSharedMemorySize, SMEM_BYTES);

    mask_kernel<<<8 * NB * NB, 256>>>(mask);
    conv_mma_kernel<<<GRID_MAIN, 256, SMEM_BYTES>>>(x, w, bias, out);
}

// round 13
// speedup vs baseline: 3.7768x; 1.1399x over previous
#include <cuda_runtime.h>
#include <cstdint>
#include <cstddef>

// SparseConv2D via mma.sync (tf32, m16n8k8) implicit GEMM, rolling-row strips.
// out(h,c,co) = sum_{ky,kx,ci} x(h+ky, c+kx, ci) * w[ky][kx][ci][co],
// gated per 14x14 block by max(mask) > 0.5 (precomputed into g_scale).
//
// R12: warp M widened to 32 px (two m16 tiles) so each B fragment load feeds
// 2 HMMAs; CTA = 128 threads / 4 warps, strip split into 18 row-chunks.

#define HIN   506
#define WIN   506
#define HOUT  504
#define WOUT  504
#define NB    36

#define NSTRIPS        32        // 8 batch * 4 column strips
#define CTAS_PER_STRIP 18
#define ROWS_PER_CTA   28        // 504 / 18
#define GRID_MAIN      (NSTRIPS * CTAS_PER_STRIP)   // 576
#define NTHREADS       128

// smem word layout (tf32 bits stored as u32):
//  ring:  3 slots of [130 px][stride 36] -> 4680 words each, 14040 total
//  BS:    swizzled B frags [9 tap][4 cc][4 s][32 lane] uint2 -> 9216 words
//  bias:  32 words
#define PATCH_STRIDE 36
#define KY_WORDS     (130 * PATCH_STRIDE)      // 4680
#define PATCH_WORDS  (3 * KY_WORDS)            // 14040
#define BS_WOFF      PATCH_WORDS               // 14040
#define BIAS_WOFF    (BS_WOFF + 9216)          // 23256
#define SMEM_WORDS   (BIAS_WOFF + 32)          // 23288
#define SMEM_BYTES   (SMEM_WORDS * 4)          // 93152

__device__ float g_scale[8 * NB * NB];

__device__ __forceinline__ uint32_t f2tf(float f) {
    uint32_t r;
    asm("cvt.rna.tf32.f32 %0, %1;" : "=r"(r) : "f"(f));
    return r;
}

__device__ __forceinline__ void mma_tf32(float* c, uint32_t a0, uint32_t a1,
                                         uint32_t a2, uint32_t a3,
                                         uint32_t b0, uint32_t b1) {
    asm volatile("mma.sync.aligned.m16n8k8.row.col.f32.tf32.tf32.f32 "
                 "{%0,%1,%2,%3}, {%4,%5,%6,%7}, {%8,%9}, {%0,%1,%2,%3};"
                 : "+f"(c[0]), "+f"(c[1]), "+f"(c[2]), "+f"(c[3])
                 : "r"(a0), "r"(a1), "r"(a2), "r"(a3), "r"(b0), "r"(b1));
}

// ---------------- mask precompute: one CTA per (n,bh,bw) ----------------
__global__ void mask_kernel(const float* __restrict__ mask) {
    __shared__ float red[8];
    int b = blockIdx.x;
    int n = b / (NB * NB);
    int rem = b % (NB * NB);
    int bh = rem / NB, bw = rem % NB;
    int tid = threadIdx.x;              // 256 = 16x16
    int r = tid >> 4, c = tid & 15;
    float m = mask[((size_t)(n * HIN + bh * 14 + r)) * WIN + bw * 14 + c];
    #pragma unroll
    for (int off = 16; off; off >>= 1)
        m = fmaxf(m, __shfl_xor_sync(0xffffffffu, m, off));
    if ((tid & 31) == 0) red[tid >> 5] = m;
    __syncthreads();
    if (tid == 0) {
        float mm = red[0];
        #pragma unroll
        for (int i = 1; i < 8; i++) mm = fmaxf(mm, red[i]);
        g_scale[b] = (mm > 0.5f) ? 1.0f : 0.0f;
    }
}

// ---------------- main persistent kernel ----------------
__global__ __launch_bounds__(NTHREADS, 2)
void conv_mma_kernel(const float* __restrict__ x,
                     const float* __restrict__ wglob,
                     const float* __restrict__ bias,
                     float* __restrict__ out)
{
    extern __shared__ uint32_t sp[];
    const int tid  = threadIdx.x;
    const int wid  = tid >> 5;      // 0..3
    const int lane = tid & 31;
    const int g    = lane >> 2;     // fragment group row 0..7
    const int tq   = lane & 3;      // thread-in-group 0..3

    // ---- strip / row-range assignment ----
    const int strip  = blockIdx.x / CTAS_PER_STRIP;       // 0..31
    const int rchunk = blockIdx.x % CTAS_PER_STRIP;       // 0..17
    const int n      = strip >> 2;                        // batch
    const int c0     = (strip & 3) << 7;                  // col base
    const int hstart = rchunk * ROWS_PER_CTA;
    const int hend   = hstart + ROWS_PER_CTA;

    // ---- build B once per CTA (stage raw weights in ring area, then swizzle) ----
    {
        const float4* w4 = reinterpret_cast<const float4*>(wglob);
        float4* st4 = reinterpret_cast<float4*>(sp);
        #pragma unroll 1
        for (int i = tid; i < 9216 / 4; i += NTHREADS)
            st4[i] = w4[i];
    }
    if (tid < 32) sp[BIAS_WOFF + tid] = __float_as_uint(bias[tid]);
    __syncthreads();
    {
        const float* stage = reinterpret_cast<const float*>(sp);
        #pragma unroll 1
        for (int idx = tid; idx < 4608; idx += NTHREADS) {
            int l   = idx & 31;
            int s   = (idx >> 5) & 3;
            int cc  = (idx >> 7) & 3;
            int tap = idx >> 9;
            int k   = cc * 8 + (l & 3);
            int nn  = s * 8 + (l >> 2);
            uint32_t b0 = f2tf(stage[tap * 1024 + k * 32 + nn]);
            uint32_t b1 = f2tf(stage[tap * 1024 + (k + 4) * 32 + nn]);
            sp[BS_WOFF + idx * 2]     = b0;
            sp[BS_WOFF + idx * 2 + 1] = b1;
        }
    }
    __syncthreads();

    // ---- initial build: input rows hstart .. hstart+2 into ring slots ----
    #pragma unroll 1
    for (int id = tid; id < 3120; id += NTHREADS) {
        int c4 = id & 7;
        int jj = id >> 3;
        int j  = jj % 130;
        int ky = jj / 130;
        int row = hstart + ky;
        int col = c0 + j; if (col > 505) col = 505;
        const float4 v = *reinterpret_cast<const float4*>(
            x + (((size_t)(n * HIN + row)) * WIN + col) * 32 + c4 * 4);
        uint32_t* dst = sp + (row % 3) * KY_WORDS + j * PATCH_STRIDE + c4 * 4;
        dst[0] = f2tf(v.x);
        dst[1] = f2tf(v.y);
        dst[2] = f2tf(v.z);
        dst[3] = f2tf(v.w);
    }
    __syncthreads();

    const int pbase = wid * 32;     // warp covers px [pbase, pbase+32)

    // ---- rolling sweep over output rows ----
    #pragma unroll 1
    for (int h = hstart; h < hend; ++h) {
        // prefetch next input row (h+3) into registers during compute
        const bool havepf = (h + 1 < hend);
        float4 pf[9];
        if (havepf) {
            const int prow = h + 3;
            #pragma unroll
            for (int k = 0; k < 9; k++) {
                int id = tid + k * NTHREADS;
                if (id < 1040) {
                    int c4 = id & 7;
                    int j  = id >> 3;
                    int col = c0 + j; if (col > 505) col = 505;
                    pf[k] = *reinterpret_cast<const float4*>(
                        x + (((size_t)(n * HIN + prow)) * WIN + col) * 32 + c4 * 4);
                }
            }
        }

        // compute: warp handles px [pbase, pbase+32) as two m16 tiles, cout 0..31
        float acc[2][4][4];
        #pragma unroll
        for (int m = 0; m < 2; m++)
            #pragma unroll
            for (int s = 0; s < 4; s++)
                #pragma unroll
                for (int i = 0; i < 4; i++) acc[m][s][i] = 0.0f;

        #pragma unroll 1
        for (int ky = 0; ky < 3; ky++) {
            const uint32_t* kbuf = sp + ((h + ky) % 3) * KY_WORDS;
            #pragma unroll
            for (int kx = 0; kx < 3; kx++) {
                const int tap = ky * 3 + kx;
                const uint32_t* arow0 = kbuf + (pbase + kx + g) * PATCH_STRIDE + tq;
                const uint32_t* arow1 = arow0 + 16 * PATCH_STRIDE;
                const uint32_t* brow = sp + BS_WOFF + tap * 1024 + lane * 2;
                #pragma unroll
                for (int cc = 0; cc < 4; cc++) {
                    uint32_t a0 = arow0[cc * 8];
                    uint32_t a1 = arow0[cc * 8 + 8 * PATCH_STRIDE];
                    uint32_t a2 = arow0[cc * 8 + 4];
                    uint32_t a3 = arow0[cc * 8 + 8 * PATCH_STRIDE + 4];
                    uint32_t a4 = arow1[cc * 8];
                    uint32_t a5 = arow1[cc * 8 + 8 * PATCH_STRIDE];
                    uint32_t a6 = arow1[cc * 8 + 4];
                    uint32_t a7 = arow1[cc * 8 + 8 * PATCH_STRIDE + 4];
                    #pragma unroll
                    for (int s = 0; s < 4; s++) {
                        const uint2 bb = *reinterpret_cast<const uint2*>(
                            brow + cc * 256 + s * 64);
                        mma_tf32(acc[0][s], a0, a1, a2, a3, bb.x, bb.y);
                        mma_tf32(acc[1][s], a4, a5, a6, a7, bb.x, bb.y);
                    }
                }
            }
        }

        // epilogue: per m-tile, thread owns px {pbase+m*16+g, +8}, couts s*8+2*tq+{0,1}
        {
            const float* bias_s = reinterpret_cast<const float*>(sp + BIAS_WOFF);
            const int srow = (n * NB + h / 14) * NB;
            #pragma unroll
            for (int m = 0; m < 2; m++) {
                const int colA = c0 + pbase + m * 16 + g;
                const int colB = colA + 8;
                float scA = 0.0f, scB = 0.0f;
                if (colA < WOUT) scA = g_scale[srow + colA / 14];
                if (colB < WOUT) scB = g_scale[srow + colB / 14];
                float* opA = out + ((size_t)(n * HOUT + h) * WOUT + colA) * 32;
                float* opB = out + ((size_t)(n * HOUT + h) * WOUT + colB) * 32;
                #pragma unroll
                for (int s = 0; s < 4; s++) {
                    const int co = s * 8 + 2 * tq;
                    const float b0 = bias_s[co], b1 = bias_s[co + 1];
                    if (colA < WOUT) {
                        float2 v = make_float2((acc[m][s][0] + b0) * scA,
                                               (acc[m][s][1] + b1) * scA);
                        *reinterpret_cast<float2*>(opA + co) = v;
                    }
                    if (colB < WOUT) {
                        float2 v = make_float2((acc[m][s][2] + b0) * scB,
                                               (acc[m][s][3] + b1) * scB);
                        *reinterpret_cast<float2*>(opB + co) = v;
                    }
                }
            }
        }

        __syncthreads();     // everyone done reading ring slot h%3

        if (havepf) {
            const int slot = h % 3;          // == (h+3) % 3
            #pragma unroll
            for (int k = 0; k < 9; k++) {
                int id = tid + k * NTHREADS;
                if (id < 1040) {
                    int c4 = id & 7;
                    int j  = id >> 3;
                    uint32_t* dst = sp + slot * KY_WORDS + j * PATCH_STRIDE + c4 * 4;
                    dst[0] = f2tf(pf[k].x);
                    dst[1] = f2tf(pf[k].y);
                    dst[2] = f2tf(pf[k].z);
                    dst[3] = f2tf(pf[k].w);
                }
            }
        }
        __syncthreads();     // new row visible before next compute
    }
}

extern "C" void kernel_launch(void* const* d_in, const int* in_sizes, int n_in,
                              void* d_out, int out_size)
{
    const float* x    = (const float*)d_in[0];
    const float* mask = (const float*)d_in[1];
    const float* w    = (const float*)d_in[2];
    const float* bias = (const float*)d_in[3];
    float* out        = (float*)d_out;
    (void)in_sizes; (void)n_in; (void)out_size;

    cudaFuncSetAttribute(conv_mma_kernel,
                         cudaFuncAttributeMaxDynamicSharedMemorySize, SMEM_BYTES);

    mask_kernel<<<8 * NB * NB, 256>>>(mask);
    conv_mma_kernel<<<GRID_MAIN, NTHREADS, SMEM_BYTES>>>(x, w, bias, out);
}